// round 14
// baseline (speedup 1.0000x reference)
#include <cuda_runtime.h>
#include <cuda_fp16.h>
#include <cstdint>

// HMMA flash attention, causal, B=4, T=4096, D=64, fp32 I/O.
// R14: V stored as single fp16 (no hi/lo) -> PV = 2 MMAs, V LDS/L2 traffic
// halved. K stays hi/lo 3-term (score accuracy). Online softmax, fp16 splits,
// BR=128 / 8 warps, 2-stage double-buffered cp.async, split-KV chunks of 8.

#define SW(o) ((o) ^ (((o) >> 3) & 0x70))

#define SM_QHI 0
#define SM_QLO (16*1024)
#define SM_STAGE0 (32*1024)
#define SM_STAGE1 (56*1024)
#define ST_KHI 0
#define ST_KLO (8*1024)
#define ST_V   (16*1024)
#define SMEM_TOTAL (80*1024)

#define KV_ELEMS (4u*4096u*64u)
__device__ __half g_qhi[KV_ELEMS];
__device__ __half g_qlo[KV_ELEMS];
__device__ __half g_khi[KV_ELEMS];
__device__ __half g_klo[KV_ELEMS];
__device__ __half g_v[KV_ELEMS];

__device__ float g_opart[8][4][4096][64];   // 33.5 MB
__device__ float g_lpart[8][4][4096];
__device__ float g_mpart[8][4][4096];

__device__ __forceinline__ uint32_t smem_u32(const void* p) {
    uint32_t a;
    asm("{ .reg .u64 t; cvta.to.shared.u64 t, %1; cvt.u32.u64 %0, t; }" : "=r"(a) : "l"(p));
    return a;
}
__device__ __forceinline__ uint2 split_pair(float x, float y) {
    __half hx = __float2half_rn(x), hy = __float2half_rn(y);
    __half lx = __float2half_rn(x - __half2float(hx));
    __half ly = __float2half_rn(y - __half2float(hy));
    uint2 r;
    r.x = (uint32_t)__half_as_ushort(hx) | ((uint32_t)__half_as_ushort(hy) << 16);
    r.y = (uint32_t)__half_as_ushort(lx) | ((uint32_t)__half_as_ushort(ly) << 16);
    return r;
}
__device__ __forceinline__ uint32_t pack_h2(float x, float y) {
    __half2 h = __floats2half2_rn(x, y);
    return *(uint32_t*)&h;
}
__device__ __forceinline__ void cp16(uint32_t dst, const void* gsrc) {
    asm volatile("cp.async.cg.shared.global [%0], [%1], 16;"
                 :: "r"(dst), "l"(__cvta_generic_to_global(gsrc)) : "memory");
}
__device__ __forceinline__ void cp_commit() {
    asm volatile("cp.async.commit_group;" ::: "memory");
}
__device__ __forceinline__ void ldm4(uint32_t r[4], uint32_t addr) {
    asm volatile("ldmatrix.sync.aligned.m8n8.x4.shared.b16 {%0,%1,%2,%3}, [%4];"
                 : "=r"(r[0]), "=r"(r[1]), "=r"(r[2]), "=r"(r[3]) : "r"(addr));
}
__device__ __forceinline__ void ldm4t(uint32_t r[4], uint32_t addr) {
    asm volatile("ldmatrix.sync.aligned.m8n8.x4.trans.shared.b16 {%0,%1,%2,%3}, [%4];"
                 : "=r"(r[0]), "=r"(r[1]), "=r"(r[2]), "=r"(r[3]) : "r"(addr));
}
__device__ __forceinline__ void mma16816(float c[4], uint32_t a0, uint32_t a1,
                                         uint32_t a2, uint32_t a3,
                                         uint32_t b0, uint32_t b1) {
    asm volatile("mma.sync.aligned.m16n8k16.row.col.f32.f16.f16.f32 "
                 "{%0,%1,%2,%3}, {%4,%5,%6,%7}, {%8,%9}, {%0,%1,%2,%3};"
                 : "+f"(c[0]), "+f"(c[1]), "+f"(c[2]), "+f"(c[3])
                 : "r"(a0), "r"(a1), "r"(a2), "r"(a3), "r"(b0), "r"(b1));
}

// ---- prep: split Q(scaled),K fp32 -> fp16 hi/lo; V -> single fp16 ----
__global__ void __launch_bounds__(256)
prep_kernel(const float4* __restrict__ Q4, const float4* __restrict__ K4,
            const float4* __restrict__ V4, const float* __restrict__ scale_p) {
    const uint32_t i = blockIdx.x * 256u + threadIdx.x;
    const float sc = scale_p[0];
    float4 q = Q4[i];
    float4 k = K4[i];
    float4 v = V4[i];
    q.x *= sc; q.y *= sc; q.z *= sc; q.w *= sc;
    uint2 qp0 = split_pair(q.x, q.y), qp1 = split_pair(q.z, q.w);
    uint2 kp0 = split_pair(k.x, k.y), kp1 = split_pair(k.z, k.w);
    ((uint2*)g_qhi)[i] = make_uint2(qp0.x, qp1.x);
    ((uint2*)g_qlo)[i] = make_uint2(qp0.y, qp1.y);
    ((uint2*)g_khi)[i] = make_uint2(kp0.x, kp1.x);
    ((uint2*)g_klo)[i] = make_uint2(kp0.y, kp1.y);
    ((uint2*)g_v)[i]   = make_uint2(pack_h2(v.x, v.y), pack_h2(v.z, v.w));
}

// load one 64-row stage (K hi/lo + V) into smem (256 threads)
__device__ __forceinline__ void cp_stage(uint32_t st, size_t gbase, int tid) {
    for (int u = tid; u < 512; u += 256) {
        int r = u >> 3, c16 = u & 7;
        size_t gs = gbase + (size_t)r * 64 + c16 * 8;
        uint32_t off = SW((uint32_t)(r * 128 + c16 * 16));
        cp16(st + ST_KHI + off, g_khi + gs);
        cp16(st + ST_KLO + off, g_klo + gs);
        cp16(st + ST_V   + off, g_v   + gs);
    }
}

// ---- main attention: 8 warps, BR=128, chunk of <=8 kv-tiles ----
__global__ void __launch_bounds__(256, 2)
attn_hmma_kernel()
{
    extern __shared__ char smem[];
    const uint32_t sb = smem_u32(smem);

    const int tid = threadIdx.x;
    const int w   = tid >> 5;
    const int l   = tid & 31;
    const int lrow  = l & 15;
    const int lcolh = l >> 4;
    const int lq    = l >> 2;
    const int lp    = l & 3;

    // unit -> (qt, s); heavy chunks first
    const int b = blockIdx.y;
    int u = 143 - (int)blockIdx.x;
    int qt = 0, cum = 0;
    for (;;) {
        int ns = (2 * qt + 9) >> 3;
        if (u < cum + ns) break;
        cum += ns; ++qt;
    }
    const int s  = u - cum;
    const int qbase  = qt * 128;
    const int ntiles = 2 * qt + 2;
    const int t0 = 8 * s;
    const int t1 = min(t0 + 8, ntiles);

    const size_t qg  = ((size_t)b * 4096 + qbase) * 64;
    const size_t kvb = (size_t)b * 4096 * 64;

    // prologue: Q + stage(t0) in G0; stage(t0+1) in G1 (if any)
    for (int u2 = tid; u2 < 1024; u2 += 256) {
        int r = u2 >> 3, c16 = u2 & 7;
        size_t gs = qg + (size_t)r * 64 + c16 * 8;
        uint32_t off = SW((uint32_t)(r * 128 + c16 * 16));
        cp16(sb + SM_QHI + off, g_qhi + gs);
        cp16(sb + SM_QLO + off, g_qlo + gs);
    }
    cp_stage(sb + SM_STAGE0, kvb + (size_t)t0 * 64 * 64, tid);
    cp_commit();
    if (t0 + 1 < t1) {
        cp_stage(sb + SM_STAGE1, kvb + (size_t)(t0 + 1) * 64 * 64, tid);
        cp_commit();
    }

    float oacc[8][4];
#pragma unroll
    for (int j = 0; j < 8; ++j)
#pragma unroll
        for (int e = 0; e < 4; ++e) oacc[j][e] = 0.f;
    float lsum0 = 0.f, lsum1 = 0.f;
    float m0 = -1e30f, m1 = -1e30f;

    const uint32_t qrow_b = (uint32_t)((16 * w + lrow) * 128);
    const uint32_t colh_b = (uint32_t)(lcolh * 16);
    const int gr0 = qbase + 16 * w + lq;   // global q row for frag c0/c1

    for (int t = t0; t < t1; ++t) {
        const uint32_t st = sb + (((t - t0) & 1) ? SM_STAGE1 : SM_STAGE0);

        if (t + 1 < t1) asm volatile("cp.async.wait_group 1;" ::: "memory");
        else            asm volatile("cp.async.wait_group 0;" ::: "memory");
        __syncthreads();

        // ---- S = Q @ K^T (3-term hi/lo) ----
        float sacc[8][4];
#pragma unroll
        for (int j = 0; j < 8; ++j)
#pragma unroll
            for (int e = 0; e < 4; ++e) sacc[j][e] = 0.f;

#pragma unroll
        for (int kc = 0; kc < 4; ++kc) {
            uint32_t qh[4], ql[4];
            uint32_t qoff = SW(qrow_b + (uint32_t)(kc * 32) + colh_b);
            ldm4(qh, sb + SM_QHI + qoff);
            ldm4(ql, sb + SM_QLO + qoff);
#pragma unroll
            for (int np = 0; np < 4; ++np) {
                uint32_t kh[4], kl[4];
                uint32_t koff = SW((uint32_t)((16 * np + lrow) * 128 + kc * 32) + colh_b);
                ldm4(kh, st + ST_KHI + koff);
                ldm4(kl, st + ST_KLO + koff);
                mma16816(sacc[2*np],   qh[0], qh[1], qh[2], qh[3], kh[0], kh[2]);
                mma16816(sacc[2*np],   qh[0], qh[1], qh[2], qh[3], kl[0], kl[2]);
                mma16816(sacc[2*np],   ql[0], ql[1], ql[2], ql[3], kh[0], kh[2]);
                mma16816(sacc[2*np+1], qh[0], qh[1], qh[2], qh[3], kh[1], kh[3]);
                mma16816(sacc[2*np+1], qh[0], qh[1], qh[2], qh[3], kl[1], kl[3]);
                mma16816(sacc[2*np+1], ql[0], ql[1], ql[2], ql[3], kh[1], kh[3]);
            }
        }

        // ---- online softmax: mask, row-max, rescale, exp, pack P fp16 ----
        const bool diag = (t >= 2 * qt);
        const int gcb = 64 * t;
        if (diag) {
#pragma unroll
            for (int j = 0; j < 8; ++j) {
                const int gc = gcb + 8 * j + 2 * lp;
                if (gc     > gr0)     sacc[j][0] = -1e30f;
                if (gc + 1 > gr0)     sacc[j][1] = -1e30f;
                if (gc     > gr0 + 8) sacc[j][2] = -1e30f;
                if (gc + 1 > gr0 + 8) sacc[j][3] = -1e30f;
            }
        }
        float tm0 = -1e30f, tm1 = -1e30f;
#pragma unroll
        for (int j = 0; j < 8; ++j) {
            tm0 = fmaxf(tm0, fmaxf(sacc[j][0], sacc[j][1]));
            tm1 = fmaxf(tm1, fmaxf(sacc[j][2], sacc[j][3]));
        }
        tm0 = fmaxf(tm0, __shfl_xor_sync(0xffffffffu, tm0, 1));
        tm0 = fmaxf(tm0, __shfl_xor_sync(0xffffffffu, tm0, 2));
        tm1 = fmaxf(tm1, __shfl_xor_sync(0xffffffffu, tm1, 1));
        tm1 = fmaxf(tm1, __shfl_xor_sync(0xffffffffu, tm1, 2));

        const float mn0 = fmaxf(m0, tm0);
        const float mn1 = fmaxf(m1, tm1);
        const float a0 = __expf(m0 - mn0);
        const float a1 = __expf(m1 - mn1);
        m0 = mn0; m1 = mn1;
        lsum0 *= a0; lsum1 *= a1;
#pragma unroll
        for (int j = 0; j < 8; ++j) {
            oacc[j][0] *= a0; oacc[j][1] *= a0;
            oacc[j][2] *= a1; oacc[j][3] *= a1;
        }

        uint32_t pa[4][4];
#pragma unroll
        for (int j = 0; j < 8; ++j) {
            float p0 = __expf(sacc[j][0] - mn0);
            float p1 = __expf(sacc[j][1] - mn0);
            float p2 = __expf(sacc[j][2] - mn1);
            float p3 = __expf(sacc[j][3] - mn1);
            lsum0 += p0 + p1;
            lsum1 += p2 + p3;
            const int jj = j >> 1, e = (j & 1) << 1;
            pa[jj][e]     = pack_h2(p0, p1);
            pa[jj][e + 1] = pack_h2(p2, p3);
        }

        // ---- O += P @ V (P fp16 x V fp16: 2 MMAs) ----
#pragma unroll
        for (int np = 0; np < 4; ++np) {
#pragma unroll
            for (int kc = 0; kc < 4; ++kc) {
                uint32_t vh[4];
                uint32_t voff = SW((uint32_t)((16 * kc + lrow) * 128 + np * 32) + colh_b);
                ldm4t(vh, st + ST_V + voff);
                mma16816(oacc[2*np],   pa[kc][0], pa[kc][1], pa[kc][2], pa[kc][3], vh[0], vh[1]);
                mma16816(oacc[2*np+1], pa[kc][0], pa[kc][1], pa[kc][2], pa[kc][3], vh[2], vh[3]);
            }
        }
        __syncthreads();   // all warps done with stage(t)

        if (t + 2 < t1) {
            cp_stage(st, kvb + (size_t)(t + 2) * 64 * 64, tid);
            cp_commit();
        }
    }

    // ---- write partials (unnormalized) + per-chunk max ----
#pragma unroll
    for (int off = 1; off < 4; off <<= 1) {
        lsum0 += __shfl_xor_sync(0xffffffffu, lsum0, off);
        lsum1 += __shfl_xor_sync(0xffffffffu, lsum1, off);
    }
    const int r0 = 16 * w + lq;
    if (lp == 0) {
        g_lpart[s][b][qbase + r0]     = lsum0;
        g_lpart[s][b][qbase + r0 + 8] = lsum1;
        g_mpart[s][b][qbase + r0]     = m0;
        g_mpart[s][b][qbase + r0 + 8] = m1;
    }
    float* P0 = &g_opart[s][b][qbase + r0][0];
    float* P1 = &g_opart[s][b][qbase + r0 + 8][0];
#pragma unroll
    for (int j = 0; j < 8; ++j) {
        const int cl = 8 * j + 2 * lp;
        *(float2*)(P0 + cl) = make_float2(oacc[j][0], oacc[j][1]);
        *(float2*)(P1 + cl) = make_float2(oacc[j][2], oacc[j][3]);
    }
}

// ---- merge: max-combine chunk partials, normalize ----
__global__ void __launch_bounds__(128)
merge_kernel(float* __restrict__ O)
{
    const int row = blockIdx.x * 8 + (threadIdx.x >> 4);   // 0..16383
    const int c4  = (threadIdx.x & 15) << 2;
    const int b = row >> 12, r = row & 4095;
    const int ns = (2 * (r >> 7) + 9) >> 3;

    float M = -1e30f;
    for (int s = 0; s < ns; ++s) M = fmaxf(M, g_mpart[s][b][r]);

    float4 acc = make_float4(0.f, 0.f, 0.f, 0.f);
    float lt = 0.f;
    for (int s = 0; s < ns; ++s) {
        const float wgt = __expf(g_mpart[s][b][r] - M);
        const float4 v = *(const float4*)&g_opart[s][b][r][c4];
        acc.x += v.x * wgt; acc.y += v.y * wgt;
        acc.z += v.z * wgt; acc.w += v.w * wgt;
        lt += g_lpart[s][b][r] * wgt;
    }
    const float inv = 1.f / lt;
    acc.x *= inv; acc.y *= inv; acc.z *= inv; acc.w *= inv;
    *(float4*)(O + (size_t)row * 64 + c4) = acc;
}

extern "C" void kernel_launch(void* const* d_in, const int* in_sizes, int n_in,
                              void* d_out, int out_size)
{
    const float* Q     = (const float*)d_in[0];
    const float* V     = (const float*)d_in[1];
    const float* K     = (const float*)d_in[2];
    const float* scale = (const float*)d_in[5];
    float* O = (float*)d_out;

    prep_kernel<<<1024, 256>>>((const float4*)Q, (const float4*)K,
                               (const float4*)V, scale);

    cudaFuncSetAttribute(attn_hmma_kernel,
                         cudaFuncAttributeMaxDynamicSharedMemorySize, SMEM_TOTAL);
    attn_hmma_kernel<<<dim3(144, 4), 256, SMEM_TOTAL>>>();

    merge_kernel<<<2048, 128>>>(O);
}

// round 16
// speedup vs baseline: 1.3441x; 1.3441x over previous
#include <cuda_runtime.h>
#include <cuda_fp16.h>
#include <cstdint>

// HMMA flash attention, causal, B=4, T=4096, D=64, fp32 I/O.
// R15 = R13 (best: 76.5us) + exp2-domain softmax (Q pre-scaled by log2e,
// __expf -> exp2f) + rescale-skip guard when row max unchanged.
// fp16 hi/lo splits; S-GEMM 3-term, PV-GEMM 2-term (P single fp16, V hi/lo).
// BR=128 / 8 warps, 2-stage double-buffered cp.async, split-KV chunks of 8.

#define SW(o) ((o) ^ (((o) >> 3) & 0x70))
#define LOG2E 1.4426950408889634f

#define SM_QHI 0
#define SM_QLO (16*1024)
#define SM_STAGE0 (32*1024)
#define SM_STAGE1 (64*1024)
#define ST_KHI 0
#define ST_KLO (8*1024)
#define ST_VHI (16*1024)
#define ST_VLO (24*1024)
#define SMEM_TOTAL (96*1024)

#define KV_ELEMS (4u*4096u*64u)
__device__ __half g_qhi[KV_ELEMS];
__device__ __half g_qlo[KV_ELEMS];
__device__ __half g_khi[KV_ELEMS];
__device__ __half g_klo[KV_ELEMS];
__device__ __half g_vhi[KV_ELEMS];
__device__ __half g_vlo[KV_ELEMS];

__device__ float g_opart[8][4][4096][64];   // 33.5 MB
__device__ float g_lpart[8][4][4096];
__device__ float g_mpart[8][4][4096];       // in log2 units

__device__ __forceinline__ uint32_t smem_u32(const void* p) {
    uint32_t a;
    asm("{ .reg .u64 t; cvta.to.shared.u64 t, %1; cvt.u32.u64 %0, t; }" : "=r"(a) : "l"(p));
    return a;
}
__device__ __forceinline__ uint2 split_pair(float x, float y) {
    __half hx = __float2half_rn(x), hy = __float2half_rn(y);
    __half lx = __float2half_rn(x - __half2float(hx));
    __half ly = __float2half_rn(y - __half2float(hy));
    uint2 r;
    r.x = (uint32_t)__half_as_ushort(hx) | ((uint32_t)__half_as_ushort(hy) << 16);
    r.y = (uint32_t)__half_as_ushort(lx) | ((uint32_t)__half_as_ushort(ly) << 16);
    return r;
}
__device__ __forceinline__ uint32_t pack_h2(float x, float y) {
    __half2 h = __floats2half2_rn(x, y);
    return *(uint32_t*)&h;
}
__device__ __forceinline__ void cp16(uint32_t dst, const void* gsrc) {
    asm volatile("cp.async.cg.shared.global [%0], [%1], 16;"
                 :: "r"(dst), "l"(__cvta_generic_to_global(gsrc)) : "memory");
}
__device__ __forceinline__ void cp_commit() {
    asm volatile("cp.async.commit_group;" ::: "memory");
}
__device__ __forceinline__ void ldm4(uint32_t r[4], uint32_t addr) {
    asm volatile("ldmatrix.sync.aligned.m8n8.x4.shared.b16 {%0,%1,%2,%3}, [%4];"
                 : "=r"(r[0]), "=r"(r[1]), "=r"(r[2]), "=r"(r[3]) : "r"(addr));
}
__device__ __forceinline__ void ldm4t(uint32_t r[4], uint32_t addr) {
    asm volatile("ldmatrix.sync.aligned.m8n8.x4.trans.shared.b16 {%0,%1,%2,%3}, [%4];"
                 : "=r"(r[0]), "=r"(r[1]), "=r"(r[2]), "=r"(r[3]) : "r"(addr));
}
__device__ __forceinline__ void mma16816(float c[4], uint32_t a0, uint32_t a1,
                                         uint32_t a2, uint32_t a3,
                                         uint32_t b0, uint32_t b1) {
    asm volatile("mma.sync.aligned.m16n8k16.row.col.f32.f16.f16.f32 "
                 "{%0,%1,%2,%3}, {%4,%5,%6,%7}, {%8,%9}, {%0,%1,%2,%3};"
                 : "+f"(c[0]), "+f"(c[1]), "+f"(c[2]), "+f"(c[3])
                 : "r"(a0), "r"(a1), "r"(a2), "r"(a3), "r"(b0), "r"(b1));
}

// ---- prep: split Q(scaled by sc*log2e),K,V fp32 -> fp16 hi/lo scratch ----
__global__ void __launch_bounds__(256)
prep_kernel(const float4* __restrict__ Q4, const float4* __restrict__ K4,
            const float4* __restrict__ V4, const float* __restrict__ scale_p) {
    const uint32_t i = blockIdx.x * 256u + threadIdx.x;
    const float sc = scale_p[0] * LOG2E;
    float4 q = Q4[i];
    float4 k = K4[i];
    float4 v = V4[i];
    q.x *= sc; q.y *= sc; q.z *= sc; q.w *= sc;
    uint2 qp0 = split_pair(q.x, q.y), qp1 = split_pair(q.z, q.w);
    uint2 kp0 = split_pair(k.x, k.y), kp1 = split_pair(k.z, k.w);
    uint2 vp0 = split_pair(v.x, v.y), vp1 = split_pair(v.z, v.w);
    ((uint2*)g_qhi)[i] = make_uint2(qp0.x, qp1.x);
    ((uint2*)g_qlo)[i] = make_uint2(qp0.y, qp1.y);
    ((uint2*)g_khi)[i] = make_uint2(kp0.x, kp1.x);
    ((uint2*)g_klo)[i] = make_uint2(kp0.y, kp1.y);
    ((uint2*)g_vhi)[i] = make_uint2(vp0.x, vp1.x);
    ((uint2*)g_vlo)[i] = make_uint2(vp0.y, vp1.y);
}

// load one 64-row K+V hi/lo stage into smem (256 threads)
__device__ __forceinline__ void cp_stage(uint32_t st, size_t gbase, int tid) {
    for (int u = tid; u < 512; u += 256) {
        int r = u >> 3, c16 = u & 7;
        size_t gs = gbase + (size_t)r * 64 + c16 * 8;
        uint32_t off = SW((uint32_t)(r * 128 + c16 * 16));
        cp16(st + ST_KHI + off, g_khi + gs);
        cp16(st + ST_KLO + off, g_klo + gs);
        cp16(st + ST_VHI + off, g_vhi + gs);
        cp16(st + ST_VLO + off, g_vlo + gs);
    }
}

// ---- main attention: 8 warps, BR=128, chunk of <=8 kv-tiles ----
__global__ void __launch_bounds__(256, 2)
attn_hmma_kernel()
{
    extern __shared__ char smem[];
    const uint32_t sb = smem_u32(smem);

    const int tid = threadIdx.x;
    const int w   = tid >> 5;
    const int l   = tid & 31;
    const int lrow  = l & 15;
    const int lcolh = l >> 4;
    const int lq    = l >> 2;
    const int lp    = l & 3;

    // unit -> (qt, s); heavy chunks first
    const int b = blockIdx.y;
    int u = 143 - (int)blockIdx.x;
    int qt = 0, cum = 0;
    for (;;) {
        int ns = (2 * qt + 9) >> 3;
        if (u < cum + ns) break;
        cum += ns; ++qt;
    }
    const int s  = u - cum;
    const int qbase  = qt * 128;
    const int ntiles = 2 * qt + 2;
    const int t0 = 8 * s;
    const int t1 = min(t0 + 8, ntiles);

    const size_t qg  = ((size_t)b * 4096 + qbase) * 64;
    const size_t kvb = (size_t)b * 4096 * 64;

    // prologue: Q + stage(t0) in G0; stage(t0+1) in G1 (if any)
    for (int u2 = tid; u2 < 1024; u2 += 256) {
        int r = u2 >> 3, c16 = u2 & 7;
        size_t gs = qg + (size_t)r * 64 + c16 * 8;
        uint32_t off = SW((uint32_t)(r * 128 + c16 * 16));
        cp16(sb + SM_QHI + off, g_qhi + gs);
        cp16(sb + SM_QLO + off, g_qlo + gs);
    }
    cp_stage(sb + SM_STAGE0, kvb + (size_t)t0 * 64 * 64, tid);
    cp_commit();
    if (t0 + 1 < t1) {
        cp_stage(sb + SM_STAGE1, kvb + (size_t)(t0 + 1) * 64 * 64, tid);
        cp_commit();
    }

    float oacc[8][4];
#pragma unroll
    for (int j = 0; j < 8; ++j)
#pragma unroll
        for (int e = 0; e < 4; ++e) oacc[j][e] = 0.f;
    float lsum0 = 0.f, lsum1 = 0.f;
    float m0 = -1e30f, m1 = -1e30f;

    const uint32_t qrow_b = (uint32_t)((16 * w + lrow) * 128);
    const uint32_t colh_b = (uint32_t)(lcolh * 16);
    const int gr0 = qbase + 16 * w + lq;   // global q row for frag c0/c1

    for (int t = t0; t < t1; ++t) {
        const uint32_t st = sb + (((t - t0) & 1) ? SM_STAGE1 : SM_STAGE0);

        if (t + 1 < t1) asm volatile("cp.async.wait_group 1;" ::: "memory");
        else            asm volatile("cp.async.wait_group 0;" ::: "memory");
        __syncthreads();

        // ---- S = Q @ K^T (3-term hi/lo), scores in log2 units ----
        float sacc[8][4];
#pragma unroll
        for (int j = 0; j < 8; ++j)
#pragma unroll
            for (int e = 0; e < 4; ++e) sacc[j][e] = 0.f;

#pragma unroll
        for (int kc = 0; kc < 4; ++kc) {
            uint32_t qh[4], ql[4];
            uint32_t qoff = SW(qrow_b + (uint32_t)(kc * 32) + colh_b);
            ldm4(qh, sb + SM_QHI + qoff);
            ldm4(ql, sb + SM_QLO + qoff);
#pragma unroll
            for (int np = 0; np < 4; ++np) {
                uint32_t kh[4], kl[4];
                uint32_t koff = SW((uint32_t)((16 * np + lrow) * 128 + kc * 32) + colh_b);
                ldm4(kh, st + ST_KHI + koff);
                ldm4(kl, st + ST_KLO + koff);
                mma16816(sacc[2*np],   qh[0], qh[1], qh[2], qh[3], kh[0], kh[2]);
                mma16816(sacc[2*np],   qh[0], qh[1], qh[2], qh[3], kl[0], kl[2]);
                mma16816(sacc[2*np],   ql[0], ql[1], ql[2], ql[3], kh[0], kh[2]);
                mma16816(sacc[2*np+1], qh[0], qh[1], qh[2], qh[3], kh[1], kh[3]);
                mma16816(sacc[2*np+1], qh[0], qh[1], qh[2], qh[3], kl[1], kl[3]);
                mma16816(sacc[2*np+1], ql[0], ql[1], ql[2], ql[3], kh[1], kh[3]);
            }
        }

        // ---- online softmax (exp2 domain): mask, row-max, rescale, pack ----
        const bool diag = (t >= 2 * qt);
        const int gcb = 64 * t;
        if (diag) {
#pragma unroll
            for (int j = 0; j < 8; ++j) {
                const int gc = gcb + 8 * j + 2 * lp;
                if (gc     > gr0)     sacc[j][0] = -1e30f;
                if (gc + 1 > gr0)     sacc[j][1] = -1e30f;
                if (gc     > gr0 + 8) sacc[j][2] = -1e30f;
                if (gc + 1 > gr0 + 8) sacc[j][3] = -1e30f;
            }
        }
        float tm0 = -1e30f, tm1 = -1e30f;
#pragma unroll
        for (int j = 0; j < 8; ++j) {
            tm0 = fmaxf(tm0, fmaxf(sacc[j][0], sacc[j][1]));
            tm1 = fmaxf(tm1, fmaxf(sacc[j][2], sacc[j][3]));
        }
        tm0 = fmaxf(tm0, __shfl_xor_sync(0xffffffffu, tm0, 1));
        tm0 = fmaxf(tm0, __shfl_xor_sync(0xffffffffu, tm0, 2));
        tm1 = fmaxf(tm1, __shfl_xor_sync(0xffffffffu, tm1, 1));
        tm1 = fmaxf(tm1, __shfl_xor_sync(0xffffffffu, tm1, 2));

        if (tm0 > m0) {
            const float a0 = exp2f(m0 - tm0);
            m0 = tm0;
            lsum0 *= a0;
#pragma unroll
            for (int j = 0; j < 8; ++j) { oacc[j][0] *= a0; oacc[j][1] *= a0; }
        }
        if (tm1 > m1) {
            const float a1 = exp2f(m1 - tm1);
            m1 = tm1;
            lsum1 *= a1;
#pragma unroll
            for (int j = 0; j < 8; ++j) { oacc[j][2] *= a1; oacc[j][3] *= a1; }
        }

        uint32_t pa[4][4];
#pragma unroll
        for (int j = 0; j < 8; ++j) {
            float p0 = exp2f(sacc[j][0] - m0);
            float p1 = exp2f(sacc[j][1] - m0);
            float p2 = exp2f(sacc[j][2] - m1);
            float p3 = exp2f(sacc[j][3] - m1);
            lsum0 += p0 + p1;
            lsum1 += p2 + p3;
            const int jj = j >> 1, e = (j & 1) << 1;
            pa[jj][e]     = pack_h2(p0, p1);
            pa[jj][e + 1] = pack_h2(p2, p3);
        }

        // ---- O += P @ V (P single fp16, V hi/lo: 2-term, 4 MMAs) ----
#pragma unroll
        for (int np = 0; np < 4; ++np) {
#pragma unroll
            for (int kc = 0; kc < 4; ++kc) {
                uint32_t vh[4], vl[4];
                uint32_t voff = SW((uint32_t)((16 * kc + lrow) * 128 + np * 32) + colh_b);
                ldm4t(vh, st + ST_VHI + voff);
                ldm4t(vl, st + ST_VLO + voff);
                mma16816(oacc[2*np],   pa[kc][0], pa[kc][1], pa[kc][2], pa[kc][3], vh[0], vh[1]);
                mma16816(oacc[2*np],   pa[kc][0], pa[kc][1], pa[kc][2], pa[kc][3], vl[0], vl[1]);
                mma16816(oacc[2*np+1], pa[kc][0], pa[kc][1], pa[kc][2], pa[kc][3], vh[2], vh[3]);
                mma16816(oacc[2*np+1], pa[kc][0], pa[kc][1], pa[kc][2], pa[kc][3], vl[2], vl[3]);
            }
        }
        __syncthreads();   // all warps done with stage(t)

        if (t + 2 < t1) {
            cp_stage(st, kvb + (size_t)(t + 2) * 64 * 64, tid);
            cp_commit();
        }
    }

    // ---- write partials (unnormalized) + per-chunk max (log2 units) ----
#pragma unroll
    for (int off = 1; off < 4; off <<= 1) {
        lsum0 += __shfl_xor_sync(0xffffffffu, lsum0, off);
        lsum1 += __shfl_xor_sync(0xffffffffu, lsum1, off);
    }
    const int r0 = 16 * w + lq;
    if (lp == 0) {
        g_lpart[s][b][qbase + r0]     = lsum0;
        g_lpart[s][b][qbase + r0 + 8] = lsum1;
        g_mpart[s][b][qbase + r0]     = m0;
        g_mpart[s][b][qbase + r0 + 8] = m1;
    }
    float* P0 = &g_opart[s][b][qbase + r0][0];
    float* P1 = &g_opart[s][b][qbase + r0 + 8][0];
#pragma unroll
    for (int j = 0; j < 8; ++j) {
        const int cl = 8 * j + 2 * lp;
        *(float2*)(P0 + cl) = make_float2(oacc[j][0], oacc[j][1]);
        *(float2*)(P1 + cl) = make_float2(oacc[j][2], oacc[j][3]);
    }
}

// ---- merge: max-combine chunk partials (exp2 domain), normalize ----
__global__ void __launch_bounds__(128)
merge_kernel(float* __restrict__ O)
{
    const int row = blockIdx.x * 8 + (threadIdx.x >> 4);   // 0..16383
    const int c4  = (threadIdx.x & 15) << 2;
    const int b = row >> 12, r = row & 4095;
    const int ns = (2 * (r >> 7) + 9) >> 3;

    float M = -1e30f;
    for (int s = 0; s < ns; ++s) M = fmaxf(M, g_mpart[s][b][r]);

    float4 acc = make_float4(0.f, 0.f, 0.f, 0.f);
    float lt = 0.f;
    for (int s = 0; s < ns; ++s) {
        const float wgt = exp2f(g_mpart[s][b][r] - M);
        const float4 v = *(const float4*)&g_opart[s][b][r][c4];
        acc.x += v.x * wgt; acc.y += v.y * wgt;
        acc.z += v.z * wgt; acc.w += v.w * wgt;
        lt += g_lpart[s][b][r] * wgt;
    }
    const float inv = 1.f / lt;
    acc.x *= inv; acc.y *= inv; acc.z *= inv; acc.w *= inv;
    *(float4*)(O + (size_t)row * 64 + c4) = acc;
}

extern "C" void kernel_launch(void* const* d_in, const int* in_sizes, int n_in,
                              void* d_out, int out_size)
{
    const float* Q     = (const float*)d_in[0];
    const float* V     = (const float*)d_in[1];
    const float* K     = (const float*)d_in[2];
    const float* scale = (const float*)d_in[5];
    float* O = (float*)d_out;

    prep_kernel<<<1024, 256>>>((const float4*)Q, (const float4*)K,
                               (const float4*)V, scale);

    cudaFuncSetAttribute(attn_hmma_kernel,
                         cudaFuncAttributeMaxDynamicSharedMemorySize, SMEM_TOTAL);
    attn_hmma_kernel<<<dim3(144, 4), 256, SMEM_TOTAL>>>();

    merge_kernel<<<2048, 128>>>(O);
}